// round 15
// baseline (speedup 1.0000x reference)
#include <cuda_runtime.h>
#include <cuda_fp16.h>
#include <cstdint>

#define N_OBS 2048
#define KH    1024
#define DIN   64
#define NTILE 8          // KH / 128
#define NPAIR 36         // upper-triangle tile pairs
#define NSPLIT 8         // split-K factor for kernelB

// Scratch (device globals: allocation-free per harness rules)
__device__ __half g_sT[KH * N_OBS];                  // 4 MB: sin activations fp16, (k, n)
__device__ float  g_Mp[NSPLIT * NPAIR * 128 * 128];  // 18.9 MB: per-(split,tile) partials (L2-resident)
__device__ __half g_wh[KH * DIN],   g_wl[KH * DIN];     // 256 KB: w hi/lo split
__device__ __half g_xh[N_OBS * DIN], g_xl[N_OBS * DIN]; // 512 KB: x hi/lo split

// ---------------------------------------------------------------------------
// Helpers (compute_103-portable)
// ---------------------------------------------------------------------------
__device__ __forceinline__ void pair_from_idx(int idx, int& tr, int& tc) {
    int t = 0, rem = idx;
    while (rem >= NTILE - t) { rem -= NTILE - t; t++; }
    tr = t; tc = t + rem;
}
__device__ __forceinline__ int idx_from_pair(int tr, int tc) {   // tr <= tc
    return tr * NTILE - (tr * (tr - 1)) / 2 + (tc - tr);
}
__device__ __forceinline__ uint32_t smem_u32(const void* p) {
    uint32_t a;
    asm("{ .reg .u64 t; cvta.to.shared.u64 t, %1; cvt.u32.u64 %0, t; }" : "=r"(a) : "l"(p));
    return a;
}
__device__ __forceinline__ void cp_async16(uint32_t dst, const void* src) {
    asm volatile("cp.async.cg.shared.global [%0], [%1], 16;" :: "r"(dst), "l"(src));
}
#define CP_COMMIT() asm volatile("cp.async.commit_group;" ::: "memory")
#define CP_WAIT1()  asm volatile("cp.async.wait_group 1;" ::: "memory")
#define CP_WAIT0()  asm volatile("cp.async.wait_group 0;" ::: "memory")

__device__ __forceinline__ void ldmatrix_x4(uint32_t* r, uint32_t addr) {
    asm volatile("ldmatrix.sync.aligned.m8n8.x4.shared.b16 {%0,%1,%2,%3}, [%4];"
                 : "=r"(r[0]), "=r"(r[1]), "=r"(r[2]), "=r"(r[3]) : "r"(addr));
}
__device__ __forceinline__ void mma_f16(float* c, const uint32_t* a, const uint32_t* b) {
    asm volatile(
        "mma.sync.aligned.m16n8k16.row.col.f32.f16.f16.f32 "
        "{%0,%1,%2,%3}, {%4,%5,%6,%7}, {%8,%9}, {%0,%1,%2,%3};"
        : "+f"(c[0]), "+f"(c[1]), "+f"(c[2]), "+f"(c[3])
        : "r"(a[0]), "r"(a[1]), "r"(a[2]), "r"(a[3]), "r"(b[0]), "r"(b[1]));
}

// FMA-pipe sine (no MUFU): Cody-Waite pi reduction + degree-9 odd Taylor.
// Valid |z| < ~1e4; max abs err ~3.6e-6 (<< fp16 storage quantization 4.9e-4).
__device__ __forceinline__ float fast_sin(float z) {
    const float INV_PI = 0.3183098861837907f;
    const float PI_HI  = 3.14159274101257324f;      // float(pi)
    const float PI_LO  = -8.74227765734758577e-8f;  // pi - PI_HI
    const int   ni = __float2int_rn(z * INV_PI);
    const float n  = (float)ni;
    float r = fmaf(-n, PI_HI, z);
    r = fmaf(-n, PI_LO, r);
    const float s2 = r * r;
    float p = fmaf(s2, 2.7557319e-6f, -1.9841270e-4f);
    p = fmaf(s2, p, 8.3333333e-3f);
    p = fmaf(s2, p, -1.6666667e-1f);
    float res = fmaf(p * s2, r, r);
    return __int_as_float(__float_as_int(res) ^ ((ni & 1) << 31));
}

// ---------------------------------------------------------------------------
// Kernel P: one-shot hi/lo fp16 split of w and x.
// ---------------------------------------------------------------------------
__global__ void __launch_bounds__(256) kernelP(const float* __restrict__ x,
                                               const float* __restrict__ w) {
    const int idx = blockIdx.x * 256 + threadIdx.x;     // float4 index
    const int WQ = KH * DIN / 4;                        // 16384 w quads
    const float4 v = (idx < WQ) ? *(const float4*)&w[idx * 4]
                                : *(const float4*)&x[(idx - WQ) * 4];
    __half h0 = __float2half_rn(v.x), h1 = __float2half_rn(v.y);
    __half h2 = __float2half_rn(v.z), h3 = __float2half_rn(v.w);
    __half l0 = __float2half_rn(v.x - __half2float(h0));
    __half l1 = __float2half_rn(v.y - __half2float(h1));
    __half l2 = __float2half_rn(v.z - __half2float(h2));
    __half l3 = __float2half_rn(v.w - __half2float(h3));
    __half2 hA = __halves2half2(h0, h1), hB = __halves2half2(h2, h3);
    __half2 lA = __halves2half2(l0, l1), lB = __halves2half2(l2, l3);
    uint2 uh; uh.x = *(uint32_t*)&hA; uh.y = *(uint32_t*)&hB;
    uint2 ul; ul.x = *(uint32_t*)&lA; ul.y = *(uint32_t*)&lB;
    if (idx < WQ) {
        *(uint2*)&g_wh[idx * 4] = uh;
        *(uint2*)&g_wl[idx * 4] = ul;
    } else {
        *(uint2*)&g_xh[(idx - WQ) * 4] = uh;
        *(uint2*)&g_xl[(idx - WQ) * 4] = ul;
    }
}

// ---------------------------------------------------------------------------
// Kernel A (split-fp16 tensor-core): g_sT[k][n] = half(fast_sin(x@w.T + b))
// z = wh*xh + wh*xl + wl*xh in fp32 (lo*lo ~2^-22, dropped).
// grid = (KH/64, N_OBS/64) = 512 CTAs, 256 thr, warp grid 2(k) x 4(n).
// ---------------------------------------------------------------------------
#define AF_ROWB 144                  // 64 halves (128 B) + 16 B pad: conflict-free
#define AF_WHI  0
#define AF_WLO  (64 * AF_ROWB)
#define AF_XHI  (2 * 64 * AF_ROWB)
#define AF_XLO  (3 * 64 * AF_ROWB)

__global__ void __launch_bounds__(256) kernelA_f16(const float* __restrict__ b) {
    __shared__ __align__(16) char smA[4 * 64 * AF_ROWB];   // 36864 B

    const uint32_t sb = smem_u32(smA);
    const int tid = threadIdx.x;
    const int wid = tid >> 5;
    const int lid = tid & 31;
    const int g   = lid >> 2;
    const int t4  = lid & 3;

    const int k0 = blockIdx.x * 64;
    const int n0 = blockIdx.y * 64;

    const int wr = wid & 1;              // k offset wr*32
    const int wc = wid >> 1;             // n offset wc*16
    const int ibase = wr * 32, nbase = wc * 16;

    for (int e = tid; e < 2048; e += 256) {
        const int which = e >> 9;                       // 0:wh 1:wl 2:xh 3:xl
        const int row   = (e >> 3) & 63;
        const int q     = e & 7;
        const __half* src;
        switch (which) {
            case 0:  src = &g_wh[(size_t)(k0 + row) * DIN + q * 8]; break;
            case 1:  src = &g_wl[(size_t)(k0 + row) * DIN + q * 8]; break;
            case 2:  src = &g_xh[(size_t)(n0 + row) * DIN + q * 8]; break;
            default: src = &g_xl[(size_t)(n0 + row) * DIN + q * 8]; break;
        }
        cp_async16(sb + (uint32_t)(which * 64 * AF_ROWB + row * AF_ROWB + q * 16), src);
    }
    CP_COMMIT();
    CP_WAIT0();
    __syncthreads();

    float c[2][2][4];
    #pragma unroll
    for (int mi = 0; mi < 2; mi++)
        #pragma unroll
        for (int ni = 0; ni < 2; ni++)
            #pragma unroll
            for (int t = 0; t < 4; t++) c[mi][ni][t] = 0.f;

    const uint32_t aOff0 = (uint32_t)((ibase + (lid & 15)) * AF_ROWB + (lid >> 4) * 16);
    const uint32_t bRow  = (uint32_t)(nbase + ((lid >> 4) << 3) + (lid & 7));
    const uint32_t bOff0 = bRow * AF_ROWB + ((lid >> 3) & 1) * 16;

    #pragma unroll
    for (int ks = 0; ks < 4; ks++) {                     // 4 x k16 over d=64
        uint32_t ah[2][4], al[2][4];
        #pragma unroll
        for (int mi = 0; mi < 2; mi++) {
            const uint32_t o = aOff0 + (uint32_t)(mi * 16 * AF_ROWB + ks * 32);
            ldmatrix_x4(ah[mi], sb + AF_WHI + o);
            ldmatrix_x4(al[mi], sb + AF_WLO + o);
        }
        uint32_t bh[4], bl[4];
        {
            const uint32_t o = bOff0 + (uint32_t)(ks * 32);
            ldmatrix_x4(bh, sb + AF_XHI + o);
            ldmatrix_x4(bl, sb + AF_XLO + o);
        }
        #pragma unroll
        for (int mi = 0; mi < 2; mi++) {
            mma_f16(c[mi][0], ah[mi], &bh[0]);   // hi*hi
            mma_f16(c[mi][0], ah[mi], &bl[0]);   // hi*lo
            mma_f16(c[mi][0], al[mi], &bh[0]);   // lo*hi
            mma_f16(c[mi][1], ah[mi], &bh[2]);
            mma_f16(c[mi][1], ah[mi], &bl[2]);
            mma_f16(c[mi][1], al[mi], &bh[2]);
        }
    }

    // Epilogue: z += b[k]; s = half(fast_sin(z)); store g_sT[k][n]
    #pragma unroll
    for (int mi = 0; mi < 2; mi++) {
        const int rr0 = k0 + ibase + 16 * mi + g;
        const float bv0 = b[rr0];
        const float bv1 = b[rr0 + 8];
        #pragma unroll
        for (int ni = 0; ni < 2; ni++) {
            const int cc = n0 + nbase + 8 * ni + 2 * t4;
            __half2 h0 = __floats2half2_rn(fast_sin(c[mi][ni][0] + bv0),
                                           fast_sin(c[mi][ni][1] + bv0));
            __half2 h1 = __floats2half2_rn(fast_sin(c[mi][ni][2] + bv1),
                                           fast_sin(c[mi][ni][3] + bv1));
            *(uint32_t*)&g_sT[(size_t)rr0 * N_OBS + cc]       = *(uint32_t*)&h0;
            *(uint32_t*)&g_sT[(size_t)(rr0 + 8) * N_OBS + cc] = *(uint32_t*)&h1;
        }
    }
}

// ---------------------------------------------------------------------------
// Kernel B: partial Gram via fp16 mma.m16n8k16 + ldmatrix.
// 3-stage cp.async pipeline, ONE __syncthreads per chunk:
//   iter ch: wait(<=1 pending) -> sync -> stage(ch+2) -> compute(ch)
// (ldmatrix is synchronous, so compute(ch-1)'s reads are complete at the sync;
// buf[(ch+2)%3] is therefore free to restage before compute(ch) issues.)
// grid = (36 pairs, 8 splits), 256 threads (8 warps 4x2, warp tile 32x64).
// ---------------------------------------------------------------------------
#define B_ROWB   80                   // 64B data + 16B pad
#define B_OPB    (128 * B_ROWB)       // 10240 B per operand tile
#define B_BUF    (2 * B_OPB)          // one (A,B) stage = 20480 B
#define B_NSTAGE 3
#define B_SMEMB  (B_NSTAGE * B_BUF)   // 61440 B dynamic
#define B_NCH    8                    // 256 n per CTA / 32 per chunk

__global__ void __launch_bounds__(256, 3) kernelB_f16() {
    extern __shared__ __align__(16) char smB[];

    const int tid = threadIdx.x;
    const int wid = tid >> 5;
    const int lid = tid & 31;
    const int g   = lid >> 2;
    const int t4  = lid & 3;

    int tr, tc; pair_from_idx(blockIdx.x, tr, tc);
    const int i0 = tr * 128, l0 = tc * 128;
    const bool diag = (tr == tc);
    const int ops  = diag ? 1 : 2;
    const int nb   = blockIdx.y * (N_OBS / NSPLIT);

    const uint32_t sb = smem_u32(smB);
    const int wr = wid & 3;
    const int wc = wid >> 2;
    const int ibase = wr * 32, lbase = wc * 64;

    float c[2][8][4];
    #pragma unroll
    for (int mi = 0; mi < 2; mi++)
        #pragma unroll
        for (int ni = 0; ni < 8; ni++)
            #pragma unroll
            for (int t = 0; t < 4; t++) c[mi][ni][t] = 0.f;

    auto stage = [&](int ch, int buf) {
        const int n0 = nb + ch * 32;
        const int tot = ops << 9;
        for (int e = tid; e < tot; e += 256) {
            const int op  = e >> 9;
            const int idx = e & 511;
            const int row = idx >> 2;
            const int c16 = idx & 3;
            const int grow = (op ? l0 : i0) + row;
            cp_async16(sb + (uint32_t)(buf * B_BUF + op * B_OPB + row * B_ROWB + c16 * 16),
                       &g_sT[(size_t)grow * N_OBS + n0 + c16 * 8]);
        }
    };

    const uint32_t aOff0 = (uint32_t)((ibase + (lid & 15)) * B_ROWB + (lid >> 4) * 16);
    const uint32_t bRow  = (uint32_t)(lbase + ((lid >> 4) << 3) + (lid & 7));
    const uint32_t bOff0 = bRow * B_ROWB + ((lid >> 3) & 1) * 16;

    stage(0, 0); CP_COMMIT();
    stage(1, 1); CP_COMMIT();

    for (int ch = 0; ch < B_NCH; ch++) {
        const int buf = ch % B_NSTAGE;
        if (ch + 1 < B_NCH) { CP_WAIT1(); }
        else                { CP_WAIT0(); }
        __syncthreads();                                 // chunk ch ready; buf[(ch+2)%3] free
        if (ch + 2 < B_NCH) { stage(ch + 2, (ch + 2) % B_NSTAGE); CP_COMMIT(); }

        const uint32_t aBase = sb + (uint32_t)(buf * B_BUF);
        const uint32_t bBase = diag ? aBase : aBase + B_OPB;

        #pragma unroll
        for (int ks = 0; ks < 2; ks++) {
            uint32_t a[2][4];
            #pragma unroll
            for (int mi = 0; mi < 2; mi++)
                ldmatrix_x4(a[mi], aBase + aOff0 + (uint32_t)(mi * 16 * B_ROWB + ks * 32));
            #pragma unroll
            for (int p = 0; p < 4; p++) {
                uint32_t bb[4];
                ldmatrix_x4(bb, bBase + bOff0 + (uint32_t)(p * 16 * B_ROWB + ks * 32));
                #pragma unroll
                for (int mi = 0; mi < 2; mi++) {
                    mma_f16(c[mi][2 * p],     a[mi], &bb[0]);
                    mma_f16(c[mi][2 * p + 1], a[mi], &bb[2]);
                }
            }
        }
    }

    const float sc = (2.0f / (float)KH) / (float)N_OBS;
    float* dst = &g_Mp[((size_t)blockIdx.y * NPAIR + blockIdx.x) * (128 * 128)];
    #pragma unroll
    for (int mi = 0; mi < 2; mi++) {
        const int rr = ibase + 16 * mi + g;
        #pragma unroll
        for (int ni = 0; ni < 8; ni++) {
            const int cc = lbase + 8 * ni + 2 * t4;
            float2 v0 = make_float2(c[mi][ni][0] * sc, c[mi][ni][1] * sc);
            float2 v1 = make_float2(c[mi][ni][2] * sc, c[mi][ni][3] * sc);
            *(float2*)&dst[(size_t)rr * 128 + cc]       = v0;
            *(float2*)&dst[(size_t)(rr + 8) * 128 + cc] = v1;
        }
    }
}

// ---------------------------------------------------------------------------
// Kernel C (fused R): Ms tile reduced from the 8 split-partials in-prologue,
// then A[d,k,l] = Ms[k,l] * w[k,d] * w[l,d]. 256 MB store-bound.
// grid = (KH/128 l-tiles, KH/8 k-blocks), 256 threads, 8 CTAs/SM.
// ---------------------------------------------------------------------------
#define C_KT 8
#define C_LT 128
#define C_WPAD 132

__global__ void __launch_bounds__(256, 8) kernelC(const float* __restrict__ w,
                                                  float* __restrict__ out) {
    __shared__ __align__(16) float wld[32][C_WPAD];     // 16.9 KB
    __shared__ __align__(16) float Ms[C_KT][C_LT];      // 4 KB
    __shared__ float wks[DIN][C_KT + 1];                // 2.3 KB

    const int tid = threadIdx.x;
    const int lt  = blockIdx.x;
    const int l0  = lt * C_LT;
    const int k0  = blockIdx.y * C_KT;
    const int kt  = k0 >> 7;
    const int ko  = k0 & 127;

    if (kt <= lt) {
        const size_t pbase = (size_t)idx_from_pair(kt, lt) * (128 * 128);
        const int kk  = tid >> 5;
        const int li4 = (tid & 31) * 4;
        float4 v = make_float4(0.f, 0.f, 0.f, 0.f);
        #pragma unroll
        for (int s = 0; s < NSPLIT; s++) {
            const float4 p = *(const float4*)
                &g_Mp[(size_t)s * NPAIR * (128 * 128) + pbase + (size_t)(ko + kk) * 128 + li4];
            v.x += p.x; v.y += p.y; v.z += p.z; v.w += p.w;
        }
        *(float4*)&Ms[kk][li4] = v;
    } else {
        const size_t pbase = (size_t)idx_from_pair(lt, kt) * (128 * 128);
        const int li = tid >> 1;
        const int h  = tid & 1;
        float4 v = make_float4(0.f, 0.f, 0.f, 0.f);
        #pragma unroll
        for (int s = 0; s < NSPLIT; s++) {
            const float4 p = *(const float4*)
                &g_Mp[(size_t)s * NPAIR * (128 * 128) + pbase + (size_t)li * 128 + ko + h * 4];
            v.x += p.x; v.y += p.y; v.z += p.z; v.w += p.w;
        }
        Ms[h * 4 + 0][li] = v.x;
        Ms[h * 4 + 1][li] = v.y;
        Ms[h * 4 + 2][li] = v.z;
        Ms[h * 4 + 3][li] = v.w;
    }

    for (int i = tid; i < C_KT * DIN; i += 256) {
        const int kk = i >> 6, d = i & 63;
        wks[d][kk] = w[(size_t)(k0 + kk) * DIN + d];
    }

    const int j     = tid >> 5;
    const int lane4 = (tid & 31) * 4;

    float4 M4;
    const size_t base = (size_t)(k0 + j) * KH + l0 + lane4;

    #pragma unroll
    for (int h = 0; h < 2; h++) {
        __syncthreads();
        for (int i = tid; i < 32 * C_LT; i += 256) {
            const int li = i >> 5, d = i & 31;
            wld[d][li] = w[(size_t)(l0 + li) * DIN + h * 32 + d];
        }
        __syncthreads();
        if (h == 0) M4 = *(const float4*)&Ms[j][lane4];

        #pragma unroll 8
        for (int dd = 0; dd < 32; dd++) {
            const int d = h * 32 + dd;
            const float wk  = wks[d][j];
            const float4 wl = *(const float4*)&wld[dd][lane4];
            float4 o;
            o.x = (M4.x * wk) * wl.x;
            o.y = (M4.y * wk) * wl.y;
            o.z = (M4.z * wk) * wl.z;
            o.w = (M4.w * wk) * wl.w;
            __stcs((float4*)&out[(size_t)d * (size_t)(KH * KH) + base], o);
        }
    }
}

// ---------------------------------------------------------------------------
extern "C" void kernel_launch(void* const* d_in, const int* in_sizes, int n_in,
                              void* d_out, int out_size) {
    (void)in_sizes; (void)n_in; (void)out_size;
    const float* x = (const float*)d_in[0];
    const float* w = (const float*)d_in[1];
    const float* b = (const float*)d_in[2];
    float* out = (float*)d_out;

    cudaFuncSetAttribute(kernelB_f16, cudaFuncAttributeMaxDynamicSharedMemorySize, B_SMEMB);

    kernelP<<<(KH * DIN + N_OBS * DIN) / (4 * 256), 256>>>(x, w);
    kernelA_f16<<<dim3(KH / 64, N_OBS / 64), 256>>>(b);
    kernelB_f16<<<dim3(NPAIR, NSPLIT), 256, B_SMEMB>>>();
    kernelC<<<dim3(KH / C_LT, KH / C_KT), 256>>>(w, out);
}

// round 16
// speedup vs baseline: 1.3907x; 1.3907x over previous
#include <cuda_runtime.h>
#include <cuda_fp16.h>
#include <cstdint>

#define N_OBS 2048
#define KH    1024
#define DIN   64
#define NTILE 8          // KH / 128
#define NPAIR 36         // upper-triangle tile pairs
#define NSPLIT 8         // split-K factor for kernelB

// Scratch (device globals: allocation-free per harness rules)
__device__ __half g_sT[KH * N_OBS];                  // 4 MB: sin activations fp16, (k, n)
__device__ float  g_Mp[NSPLIT * NPAIR * 128 * 128];  // 18.9 MB: per-(split,tile) partials (L2-resident)
__device__ __half g_wh[KH * DIN],   g_wl[KH * DIN];     // 256 KB: w hi/lo split
__device__ __half g_xh[N_OBS * DIN], g_xl[N_OBS * DIN]; // 512 KB: x hi/lo split

// ---------------------------------------------------------------------------
// Helpers (compute_103-portable)
// ---------------------------------------------------------------------------
__device__ __forceinline__ void pair_from_idx(int idx, int& tr, int& tc) {
    int t = 0, rem = idx;
    while (rem >= NTILE - t) { rem -= NTILE - t; t++; }
    tr = t; tc = t + rem;
}
__device__ __forceinline__ int idx_from_pair(int tr, int tc) {   // tr <= tc
    return tr * NTILE - (tr * (tr - 1)) / 2 + (tc - tr);
}
__device__ __forceinline__ uint32_t smem_u32(const void* p) {
    uint32_t a;
    asm("{ .reg .u64 t; cvta.to.shared.u64 t, %1; cvt.u32.u64 %0, t; }" : "=r"(a) : "l"(p));
    return a;
}
__device__ __forceinline__ void cp_async16(uint32_t dst, const void* src) {
    asm volatile("cp.async.cg.shared.global [%0], [%1], 16;" :: "r"(dst), "l"(src));
}
#define CP_COMMIT() asm volatile("cp.async.commit_group;" ::: "memory")
#define CP_WAIT1()  asm volatile("cp.async.wait_group 1;" ::: "memory")
#define CP_WAIT0()  asm volatile("cp.async.wait_group 0;" ::: "memory")

__device__ __forceinline__ void ldmatrix_x4(uint32_t* r, uint32_t addr) {
    asm volatile("ldmatrix.sync.aligned.m8n8.x4.shared.b16 {%0,%1,%2,%3}, [%4];"
                 : "=r"(r[0]), "=r"(r[1]), "=r"(r[2]), "=r"(r[3]) : "r"(addr));
}
__device__ __forceinline__ void mma_f16(float* c, const uint32_t* a, const uint32_t* b) {
    asm volatile(
        "mma.sync.aligned.m16n8k16.row.col.f32.f16.f16.f32 "
        "{%0,%1,%2,%3}, {%4,%5,%6,%7}, {%8,%9}, {%0,%1,%2,%3};"
        : "+f"(c[0]), "+f"(c[1]), "+f"(c[2]), "+f"(c[3])
        : "r"(a[0]), "r"(a[1]), "r"(a[2]), "r"(a[3]), "r"(b[0]), "r"(b[1]));
}

// FMA-pipe sine (no MUFU): Cody-Waite pi reduction + degree-9 odd Taylor.
// Valid |z| < ~1e4; max abs err ~3.6e-6 (<< fp16 storage quantization 4.9e-4).
__device__ __forceinline__ float fast_sin(float z) {
    const float INV_PI = 0.3183098861837907f;
    const float PI_HI  = 3.14159274101257324f;      // float(pi)
    const float PI_LO  = -8.74227765734758577e-8f;  // pi - PI_HI
    const int   ni = __float2int_rn(z * INV_PI);
    const float n  = (float)ni;
    float r = fmaf(-n, PI_HI, z);
    r = fmaf(-n, PI_LO, r);
    const float s2 = r * r;
    float p = fmaf(s2, 2.7557319e-6f, -1.9841270e-4f);
    p = fmaf(s2, p, 8.3333333e-3f);
    p = fmaf(s2, p, -1.6666667e-1f);
    float res = fmaf(p * s2, r, r);
    return __int_as_float(__float_as_int(res) ^ ((ni & 1) << 31));
}

// ---------------------------------------------------------------------------
// Kernel P: one-shot hi/lo fp16 split of w and x.
// ---------------------------------------------------------------------------
__global__ void __launch_bounds__(256) kernelP(const float* __restrict__ x,
                                               const float* __restrict__ w) {
    const int idx = blockIdx.x * 256 + threadIdx.x;     // float4 index
    const int WQ = KH * DIN / 4;                        // 16384 w quads
    const float4 v = (idx < WQ) ? *(const float4*)&w[idx * 4]
                                : *(const float4*)&x[(idx - WQ) * 4];
    __half h0 = __float2half_rn(v.x), h1 = __float2half_rn(v.y);
    __half h2 = __float2half_rn(v.z), h3 = __float2half_rn(v.w);
    __half l0 = __float2half_rn(v.x - __half2float(h0));
    __half l1 = __float2half_rn(v.y - __half2float(h1));
    __half l2 = __float2half_rn(v.z - __half2float(h2));
    __half l3 = __float2half_rn(v.w - __half2float(h3));
    __half2 hA = __halves2half2(h0, h1), hB = __halves2half2(h2, h3);
    __half2 lA = __halves2half2(l0, l1), lB = __halves2half2(l2, l3);
    uint2 uh; uh.x = *(uint32_t*)&hA; uh.y = *(uint32_t*)&hB;
    uint2 ul; ul.x = *(uint32_t*)&lA; ul.y = *(uint32_t*)&lB;
    if (idx < WQ) {
        *(uint2*)&g_wh[idx * 4] = uh;
        *(uint2*)&g_wl[idx * 4] = ul;
    } else {
        *(uint2*)&g_xh[(idx - WQ) * 4] = uh;
        *(uint2*)&g_xl[(idx - WQ) * 4] = ul;
    }
}

// ---------------------------------------------------------------------------
// Kernel A (split-fp16 tensor-core): g_sT[k][n] = half(fast_sin(x@w.T + b))
// z = wh*xh + wh*xl + wl*xh in fp32 (lo*lo ~2^-22, dropped).
// grid = (KH/64, N_OBS/64) = 512 CTAs, 256 thr, warp grid 2(k) x 4(n).
// ---------------------------------------------------------------------------
#define AF_ROWB 144                  // 64 halves (128 B) + 16 B pad: conflict-free
#define AF_WHI  0
#define AF_WLO  (64 * AF_ROWB)
#define AF_XHI  (2 * 64 * AF_ROWB)
#define AF_XLO  (3 * 64 * AF_ROWB)

__global__ void __launch_bounds__(256) kernelA_f16(const float* __restrict__ b) {
    __shared__ __align__(16) char smA[4 * 64 * AF_ROWB];   // 36864 B

    const uint32_t sb = smem_u32(smA);
    const int tid = threadIdx.x;
    const int wid = tid >> 5;
    const int lid = tid & 31;
    const int g   = lid >> 2;
    const int t4  = lid & 3;

    const int k0 = blockIdx.x * 64;
    const int n0 = blockIdx.y * 64;

    const int wr = wid & 1;              // k offset wr*32
    const int wc = wid >> 1;             // n offset wc*16
    const int ibase = wr * 32, nbase = wc * 16;

    for (int e = tid; e < 2048; e += 256) {
        const int which = e >> 9;                       // 0:wh 1:wl 2:xh 3:xl
        const int row   = (e >> 3) & 63;
        const int q     = e & 7;
        const __half* src;
        switch (which) {
            case 0:  src = &g_wh[(size_t)(k0 + row) * DIN + q * 8]; break;
            case 1:  src = &g_wl[(size_t)(k0 + row) * DIN + q * 8]; break;
            case 2:  src = &g_xh[(size_t)(n0 + row) * DIN + q * 8]; break;
            default: src = &g_xl[(size_t)(n0 + row) * DIN + q * 8]; break;
        }
        cp_async16(sb + (uint32_t)(which * 64 * AF_ROWB + row * AF_ROWB + q * 16), src);
    }
    CP_COMMIT();
    CP_WAIT0();
    __syncthreads();

    float c[2][2][4];
    #pragma unroll
    for (int mi = 0; mi < 2; mi++)
        #pragma unroll
        for (int ni = 0; ni < 2; ni++)
            #pragma unroll
            for (int t = 0; t < 4; t++) c[mi][ni][t] = 0.f;

    const uint32_t aOff0 = (uint32_t)((ibase + (lid & 15)) * AF_ROWB + (lid >> 4) * 16);
    const uint32_t bRow  = (uint32_t)(nbase + ((lid >> 4) << 3) + (lid & 7));
    const uint32_t bOff0 = bRow * AF_ROWB + ((lid >> 3) & 1) * 16;

    #pragma unroll
    for (int ks = 0; ks < 4; ks++) {                     // 4 x k16 over d=64
        uint32_t ah[2][4], al[2][4];
        #pragma unroll
        for (int mi = 0; mi < 2; mi++) {
            const uint32_t o = aOff0 + (uint32_t)(mi * 16 * AF_ROWB + ks * 32);
            ldmatrix_x4(ah[mi], sb + AF_WHI + o);
            ldmatrix_x4(al[mi], sb + AF_WLO + o);
        }
        uint32_t bh[4], bl[4];
        {
            const uint32_t o = bOff0 + (uint32_t)(ks * 32);
            ldmatrix_x4(bh, sb + AF_XHI + o);
            ldmatrix_x4(bl, sb + AF_XLO + o);
        }
        #pragma unroll
        for (int mi = 0; mi < 2; mi++) {
            mma_f16(c[mi][0], ah[mi], &bh[0]);   // hi*hi
            mma_f16(c[mi][0], ah[mi], &bl[0]);   // hi*lo
            mma_f16(c[mi][0], al[mi], &bh[0]);   // lo*hi
            mma_f16(c[mi][1], ah[mi], &bh[2]);
            mma_f16(c[mi][1], ah[mi], &bl[2]);
            mma_f16(c[mi][1], al[mi], &bh[2]);
        }
    }

    // Epilogue: z += b[k]; s = half(fast_sin(z)); store g_sT[k][n]
    #pragma unroll
    for (int mi = 0; mi < 2; mi++) {
        const int rr0 = k0 + ibase + 16 * mi + g;
        const float bv0 = b[rr0];
        const float bv1 = b[rr0 + 8];
        #pragma unroll
        for (int ni = 0; ni < 2; ni++) {
            const int cc = n0 + nbase + 8 * ni + 2 * t4;
            __half2 h0 = __floats2half2_rn(fast_sin(c[mi][ni][0] + bv0),
                                           fast_sin(c[mi][ni][1] + bv0));
            __half2 h1 = __floats2half2_rn(fast_sin(c[mi][ni][2] + bv1),
                                           fast_sin(c[mi][ni][3] + bv1));
            *(uint32_t*)&g_sT[(size_t)rr0 * N_OBS + cc]       = *(uint32_t*)&h0;
            *(uint32_t*)&g_sT[(size_t)(rr0 + 8) * N_OBS + cc] = *(uint32_t*)&h1;
        }
    }
}

// ---------------------------------------------------------------------------
// Kernel B: partial Gram via fp16 mma.m16n8k16 + ldmatrix, cp.async dbl-buffer
// (two-barrier per chunk — the proven round-12/14 configuration).
// grid = (36 pairs, 8 splits), 256 threads (8 warps 4x2, warp tile 32x64).
// ---------------------------------------------------------------------------
#define B_ROWB  80                    // 64B data + 16B pad
#define B_OPB   (128 * B_ROWB)
#define B_BUF   (2 * B_OPB)
#define B_SMEMB (2 * B_BUF)           // 40960 B double-buffered
#define B_NCH   8                     // 256 n per CTA / 32 per chunk

__global__ void __launch_bounds__(256, 3) kernelB_f16() {
    __shared__ __align__(16) char sm[B_SMEMB];

    const int tid = threadIdx.x;
    const int wid = tid >> 5;
    const int lid = tid & 31;
    const int g   = lid >> 2;
    const int t4  = lid & 3;

    int tr, tc; pair_from_idx(blockIdx.x, tr, tc);
    const int i0 = tr * 128, l0 = tc * 128;
    const bool diag = (tr == tc);
    const int ops  = diag ? 1 : 2;
    const int nb   = blockIdx.y * (N_OBS / NSPLIT);

    const uint32_t sb = smem_u32(sm);
    const int wr = wid & 3;
    const int wc = wid >> 2;
    const int ibase = wr * 32, lbase = wc * 64;

    float c[2][8][4];
    #pragma unroll
    for (int mi = 0; mi < 2; mi++)
        #pragma unroll
        for (int ni = 0; ni < 8; ni++)
            #pragma unroll
            for (int t = 0; t < 4; t++) c[mi][ni][t] = 0.f;

    auto stage = [&](int ch, int buf) {
        const int n0 = nb + ch * 32;
        const int tot = ops << 9;
        for (int e = tid; e < tot; e += 256) {
            const int op  = e >> 9;
            const int idx = e & 511;
            const int row = idx >> 2;
            const int c16 = idx & 3;
            const int grow = (op ? l0 : i0) + row;
            cp_async16(sb + (uint32_t)(buf * B_BUF + op * B_OPB + row * B_ROWB + c16 * 16),
                       &g_sT[(size_t)grow * N_OBS + n0 + c16 * 8]);
        }
    };

    const uint32_t aOff0 = (uint32_t)((ibase + (lid & 15)) * B_ROWB + (lid >> 4) * 16);
    const uint32_t bRow  = (uint32_t)(lbase + ((lid >> 4) << 3) + (lid & 7));
    const uint32_t bOff0 = bRow * B_ROWB + ((lid >> 3) & 1) * 16;

    stage(0, 0);
    CP_COMMIT();

    for (int ch = 0; ch < B_NCH; ch++) {
        const int buf = ch & 1;
        if (ch + 1 < B_NCH) { stage(ch + 1, buf ^ 1); CP_COMMIT(); CP_WAIT1(); }
        else                { CP_WAIT0(); }
        __syncthreads();

        const uint32_t aBase = sb + buf * B_BUF;
        const uint32_t bBase = diag ? aBase : aBase + B_OPB;

        #pragma unroll
        for (int ks = 0; ks < 2; ks++) {
            uint32_t a[2][4];
            #pragma unroll
            for (int mi = 0; mi < 2; mi++)
                ldmatrix_x4(a[mi], aBase + aOff0 + (uint32_t)(mi * 16 * B_ROWB + ks * 32));
            #pragma unroll
            for (int p = 0; p < 4; p++) {
                uint32_t bb[4];
                ldmatrix_x4(bb, bBase + bOff0 + (uint32_t)(p * 16 * B_ROWB + ks * 32));
                #pragma unroll
                for (int mi = 0; mi < 2; mi++) {
                    mma_f16(c[mi][2 * p],     a[mi], &bb[0]);
                    mma_f16(c[mi][2 * p + 1], a[mi], &bb[2]);
                }
            }
        }
        __syncthreads();
    }

    const float sc = (2.0f / (float)KH) / (float)N_OBS;
    float* dst = &g_Mp[((size_t)blockIdx.y * NPAIR + blockIdx.x) * (128 * 128)];
    #pragma unroll
    for (int mi = 0; mi < 2; mi++) {
        const int rr = ibase + 16 * mi + g;
        #pragma unroll
        for (int ni = 0; ni < 8; ni++) {
            const int cc = lbase + 8 * ni + 2 * t4;
            float2 v0 = make_float2(c[mi][ni][0] * sc, c[mi][ni][1] * sc);
            float2 v1 = make_float2(c[mi][ni][2] * sc, c[mi][ni][3] * sc);
            *(float2*)&dst[(size_t)rr * 128 + cc]       = v0;
            *(float2*)&dst[(size_t)(rr + 8) * 128 + cc] = v1;
        }
    }
}

// ---------------------------------------------------------------------------
// Kernel C (fused R): Ms tile reduced from the 8 split-partials in-prologue,
// then A[d,k,l] = Ms[k,l] * w[k,d] * w[l,d]. 256 MB store-bound.
// grid = (KH/128 l-tiles, KH/8 k-blocks), 256 threads, 8 CTAs/SM.
// ---------------------------------------------------------------------------
#define C_KT 8
#define C_LT 128
#define C_WPAD 132

__global__ void __launch_bounds__(256, 8) kernelC(const float* __restrict__ w,
                                                  float* __restrict__ out) {
    __shared__ __align__(16) float wld[32][C_WPAD];     // 16.9 KB
    __shared__ __align__(16) float Ms[C_KT][C_LT];      // 4 KB
    __shared__ float wks[DIN][C_KT + 1];                // 2.3 KB

    const int tid = threadIdx.x;
    const int lt  = blockIdx.x;
    const int l0  = lt * C_LT;
    const int k0  = blockIdx.y * C_KT;
    const int kt  = k0 >> 7;
    const int ko  = k0 & 127;

    if (kt <= lt) {
        const size_t pbase = (size_t)idx_from_pair(kt, lt) * (128 * 128);
        const int kk  = tid >> 5;
        const int li4 = (tid & 31) * 4;
        float4 v = make_float4(0.f, 0.f, 0.f, 0.f);
        #pragma unroll
        for (int s = 0; s < NSPLIT; s++) {
            const float4 p = *(const float4*)
                &g_Mp[(size_t)s * NPAIR * (128 * 128) + pbase + (size_t)(ko + kk) * 128 + li4];
            v.x += p.x; v.y += p.y; v.z += p.z; v.w += p.w;
        }
        *(float4*)&Ms[kk][li4] = v;
    } else {
        const size_t pbase = (size_t)idx_from_pair(lt, kt) * (128 * 128);
        const int li = tid >> 1;
        const int h  = tid & 1;
        float4 v = make_float4(0.f, 0.f, 0.f, 0.f);
        #pragma unroll
        for (int s = 0; s < NSPLIT; s++) {
            const float4 p = *(const float4*)
                &g_Mp[(size_t)s * NPAIR * (128 * 128) + pbase + (size_t)li * 128 + ko + h * 4];
            v.x += p.x; v.y += p.y; v.z += p.z; v.w += p.w;
        }
        Ms[h * 4 + 0][li] = v.x;
        Ms[h * 4 + 1][li] = v.y;
        Ms[h * 4 + 2][li] = v.z;
        Ms[h * 4 + 3][li] = v.w;
    }

    for (int i = tid; i < C_KT * DIN; i += 256) {
        const int kk = i >> 6, d = i & 63;
        wks[d][kk] = w[(size_t)(k0 + kk) * DIN + d];
    }

    const int j     = tid >> 5;
    const int lane4 = (tid & 31) * 4;

    float4 M4;
    const size_t base = (size_t)(k0 + j) * KH + l0 + lane4;

    #pragma unroll
    for (int h = 0; h < 2; h++) {
        __syncthreads();
        for (int i = tid; i < 32 * C_LT; i += 256) {
            const int li = i >> 5, d = i & 31;
            wld[d][li] = w[(size_t)(l0 + li) * DIN + h * 32 + d];
        }
        __syncthreads();
        if (h == 0) M4 = *(const float4*)&Ms[j][lane4];

        #pragma unroll 8
        for (int dd = 0; dd < 32; dd++) {
            const int d = h * 32 + dd;
            const float wk  = wks[d][j];
            const float4 wl = *(const float4*)&wld[dd][lane4];
            float4 o;
            o.x = (M4.x * wk) * wl.x;
            o.y = (M4.y * wk) * wl.y;
            o.z = (M4.z * wk) * wl.z;
            o.w = (M4.w * wk) * wl.w;
            __stcs((float4*)&out[(size_t)d * (size_t)(KH * KH) + base], o);
        }
    }
}

// ---------------------------------------------------------------------------
extern "C" void kernel_launch(void* const* d_in, const int* in_sizes, int n_in,
                              void* d_out, int out_size) {
    (void)in_sizes; (void)n_in; (void)out_size;
    const float* x = (const float*)d_in[0];
    const float* w = (const float*)d_in[1];
    const float* b = (const float*)d_in[2];
    float* out = (float*)d_out;

    kernelP<<<(KH * DIN + N_OBS * DIN) / (4 * 256), 256>>>(x, w);
    kernelA_f16<<<dim3(KH / 64, N_OBS / 64), 256>>>(b);
    kernelB_f16<<<dim3(NPAIR, NSPLIT), 256>>>();
    kernelC<<<dim3(KH / C_LT, KH / C_KT), 256>>>(w, out);
}

// round 17
// speedup vs baseline: 1.4172x; 1.0191x over previous
#include <cuda_runtime.h>
#include <cuda_fp16.h>
#include <cstdint>

#define N_OBS 2048
#define KH    1024
#define DIN   64
#define NTILE 8          // KH / 128
#define NPAIR 36         // upper-triangle tile pairs
#define NSPLIT 8         // split-K factor for kernelB

// Scratch (device globals: allocation-free per harness rules)
__device__ __half g_sT[KH * N_OBS];                  // 4 MB: sin activations fp16, (k, n)
__device__ float  g_Mp[NSPLIT * NPAIR * 128 * 128];  // 18.9 MB: per-(split,tile) partials (L2-resident)
__device__ __half g_wh[KH * DIN],   g_wl[KH * DIN];     // 256 KB: w hi/lo split
__device__ __half g_xh[N_OBS * DIN], g_xl[N_OBS * DIN]; // 512 KB: x hi/lo split

// ---------------------------------------------------------------------------
// Helpers (compute_103-portable)
// ---------------------------------------------------------------------------
__device__ __forceinline__ void pair_from_idx(int idx, int& tr, int& tc) {
    int t = 0, rem = idx;
    while (rem >= NTILE - t) { rem -= NTILE - t; t++; }
    tr = t; tc = t + rem;
}
__device__ __forceinline__ int idx_from_pair(int tr, int tc) {   // tr <= tc
    return tr * NTILE - (tr * (tr - 1)) / 2 + (tc - tr);
}
__device__ __forceinline__ uint32_t smem_u32(const void* p) {
    uint32_t a;
    asm("{ .reg .u64 t; cvta.to.shared.u64 t, %1; cvt.u32.u64 %0, t; }" : "=r"(a) : "l"(p));
    return a;
}
__device__ __forceinline__ void cp_async16(uint32_t dst, const void* src) {
    asm volatile("cp.async.cg.shared.global [%0], [%1], 16;" :: "r"(dst), "l"(src));
}
#define CP_COMMIT() asm volatile("cp.async.commit_group;" ::: "memory")
#define CP_WAIT1()  asm volatile("cp.async.wait_group 1;" ::: "memory")
#define CP_WAIT0()  asm volatile("cp.async.wait_group 0;" ::: "memory")

__device__ __forceinline__ void ldmatrix_x4(uint32_t* r, uint32_t addr) {
    asm volatile("ldmatrix.sync.aligned.m8n8.x4.shared.b16 {%0,%1,%2,%3}, [%4];"
                 : "=r"(r[0]), "=r"(r[1]), "=r"(r[2]), "=r"(r[3]) : "r"(addr));
}
__device__ __forceinline__ void mma_f16(float* c, const uint32_t* a, const uint32_t* b) {
    asm volatile(
        "mma.sync.aligned.m16n8k16.row.col.f32.f16.f16.f32 "
        "{%0,%1,%2,%3}, {%4,%5,%6,%7}, {%8,%9}, {%0,%1,%2,%3};"
        : "+f"(c[0]), "+f"(c[1]), "+f"(c[2]), "+f"(c[3])
        : "r"(a[0]), "r"(a[1]), "r"(a[2]), "r"(a[3]), "r"(b[0]), "r"(b[1]));
}

// FMA-pipe sine (no MUFU): Cody-Waite pi reduction + degree-9 odd Taylor.
__device__ __forceinline__ float fast_sin(float z) {
    const float INV_PI = 0.3183098861837907f;
    const float PI_HI  = 3.14159274101257324f;
    const float PI_LO  = -8.74227765734758577e-8f;
    const int   ni = __float2int_rn(z * INV_PI);
    const float n  = (float)ni;
    float r = fmaf(-n, PI_HI, z);
    r = fmaf(-n, PI_LO, r);
    const float s2 = r * r;
    float p = fmaf(s2, 2.7557319e-6f, -1.9841270e-4f);
    p = fmaf(s2, p, 8.3333333e-3f);
    p = fmaf(s2, p, -1.6666667e-1f);
    float res = fmaf(p * s2, r, r);
    return __int_as_float(__float_as_int(res) ^ ((ni & 1) << 31));
}

// ---------------------------------------------------------------------------
// Kernel P: one-shot hi/lo fp16 split of w and x.
// ---------------------------------------------------------------------------
__global__ void __launch_bounds__(256) kernelP(const float* __restrict__ x,
                                               const float* __restrict__ w) {
    const int idx = blockIdx.x * 256 + threadIdx.x;     // float4 index
    const int WQ = KH * DIN / 4;
    const float4 v = (idx < WQ) ? *(const float4*)&w[idx * 4]
                                : *(const float4*)&x[(idx - WQ) * 4];
    __half h0 = __float2half_rn(v.x), h1 = __float2half_rn(v.y);
    __half h2 = __float2half_rn(v.z), h3 = __float2half_rn(v.w);
    __half l0 = __float2half_rn(v.x - __half2float(h0));
    __half l1 = __float2half_rn(v.y - __half2float(h1));
    __half l2 = __float2half_rn(v.z - __half2float(h2));
    __half l3 = __float2half_rn(v.w - __half2float(h3));
    __half2 hA = __halves2half2(h0, h1), hB = __halves2half2(h2, h3);
    __half2 lA = __halves2half2(l0, l1), lB = __halves2half2(l2, l3);
    uint2 uh; uh.x = *(uint32_t*)&hA; uh.y = *(uint32_t*)&hB;
    uint2 ul; ul.x = *(uint32_t*)&lA; ul.y = *(uint32_t*)&lB;
    if (idx < WQ) {
        *(uint2*)&g_wh[idx * 4] = uh;
        *(uint2*)&g_wl[idx * 4] = ul;
    } else {
        *(uint2*)&g_xh[(idx - WQ) * 4] = uh;
        *(uint2*)&g_xl[(idx - WQ) * 4] = ul;
    }
}

// ---------------------------------------------------------------------------
// Kernel A (split-fp16 tensor-core): g_sT[k][n] = half(fast_sin(x@w.T + b))
// grid = (KH/64, N_OBS/64) = 512 CTAs, 256 thr, warp grid 2(k) x 4(n).
// ---------------------------------------------------------------------------
#define AF_ROWB 144
#define AF_WHI  0
#define AF_WLO  (64 * AF_ROWB)
#define AF_XHI  (2 * 64 * AF_ROWB)
#define AF_XLO  (3 * 64 * AF_ROWB)

__global__ void __launch_bounds__(256) kernelA_f16(const float* __restrict__ b) {
    __shared__ __align__(16) char smA[4 * 64 * AF_ROWB];   // 36864 B

    const uint32_t sb = smem_u32(smA);
    const int tid = threadIdx.x;
    const int wid = tid >> 5;
    const int lid = tid & 31;
    const int g   = lid >> 2;
    const int t4  = lid & 3;

    const int k0 = blockIdx.x * 64;
    const int n0 = blockIdx.y * 64;

    const int wr = wid & 1;
    const int wc = wid >> 1;
    const int ibase = wr * 32, nbase = wc * 16;

    for (int e = tid; e < 2048; e += 256) {
        const int which = e >> 9;
        const int row   = (e >> 3) & 63;
        const int q     = e & 7;
        const __half* src;
        switch (which) {
            case 0:  src = &g_wh[(size_t)(k0 + row) * DIN + q * 8]; break;
            case 1:  src = &g_wl[(size_t)(k0 + row) * DIN + q * 8]; break;
            case 2:  src = &g_xh[(size_t)(n0 + row) * DIN + q * 8]; break;
            default: src = &g_xl[(size_t)(n0 + row) * DIN + q * 8]; break;
        }
        cp_async16(sb + (uint32_t)(which * 64 * AF_ROWB + row * AF_ROWB + q * 16), src);
    }
    CP_COMMIT();
    CP_WAIT0();
    __syncthreads();

    float c[2][2][4];
    #pragma unroll
    for (int mi = 0; mi < 2; mi++)
        #pragma unroll
        for (int ni = 0; ni < 2; ni++)
            #pragma unroll
            for (int t = 0; t < 4; t++) c[mi][ni][t] = 0.f;

    const uint32_t aOff0 = (uint32_t)((ibase + (lid & 15)) * AF_ROWB + (lid >> 4) * 16);
    const uint32_t bRow  = (uint32_t)(nbase + ((lid >> 4) << 3) + (lid & 7));
    const uint32_t bOff0 = bRow * AF_ROWB + ((lid >> 3) & 1) * 16;

    #pragma unroll
    for (int ks = 0; ks < 4; ks++) {
        uint32_t ah[2][4], al[2][4];
        #pragma unroll
        for (int mi = 0; mi < 2; mi++) {
            const uint32_t o = aOff0 + (uint32_t)(mi * 16 * AF_ROWB + ks * 32);
            ldmatrix_x4(ah[mi], sb + AF_WHI + o);
            ldmatrix_x4(al[mi], sb + AF_WLO + o);
        }
        uint32_t bh[4], bl[4];
        {
            const uint32_t o = bOff0 + (uint32_t)(ks * 32);
            ldmatrix_x4(bh, sb + AF_XHI + o);
            ldmatrix_x4(bl, sb + AF_XLO + o);
        }
        #pragma unroll
        for (int mi = 0; mi < 2; mi++) {
            mma_f16(c[mi][0], ah[mi], &bh[0]);
            mma_f16(c[mi][0], ah[mi], &bl[0]);
            mma_f16(c[mi][0], al[mi], &bh[0]);
            mma_f16(c[mi][1], ah[mi], &bh[2]);
            mma_f16(c[mi][1], ah[mi], &bl[2]);
            mma_f16(c[mi][1], al[mi], &bh[2]);
        }
    }

    #pragma unroll
    for (int mi = 0; mi < 2; mi++) {
        const int rr0 = k0 + ibase + 16 * mi + g;
        const float bv0 = b[rr0];
        const float bv1 = b[rr0 + 8];
        #pragma unroll
        for (int ni = 0; ni < 2; ni++) {
            const int cc = n0 + nbase + 8 * ni + 2 * t4;
            __half2 h0 = __floats2half2_rn(fast_sin(c[mi][ni][0] + bv0),
                                           fast_sin(c[mi][ni][1] + bv0));
            __half2 h1 = __floats2half2_rn(fast_sin(c[mi][ni][2] + bv1),
                                           fast_sin(c[mi][ni][3] + bv1));
            *(uint32_t*)&g_sT[(size_t)rr0 * N_OBS + cc]       = *(uint32_t*)&h0;
            *(uint32_t*)&g_sT[(size_t)(rr0 + 8) * N_OBS + cc] = *(uint32_t*)&h1;
        }
    }
}

// ---------------------------------------------------------------------------
// Kernel B: partial Gram via fp16 mma.m16n8k16 + ldmatrix, cp.async dbl-buffer
// (two-barrier per chunk — proven configuration, unchanged).
// ---------------------------------------------------------------------------
#define B_ROWB  80
#define B_OPB   (128 * B_ROWB)
#define B_BUF   (2 * B_OPB)
#define B_SMEMB (2 * B_BUF)
#define B_NCH   8

__global__ void __launch_bounds__(256, 3) kernelB_f16() {
    __shared__ __align__(16) char sm[B_SMEMB];

    const int tid = threadIdx.x;
    const int wid = tid >> 5;
    const int lid = tid & 31;
    const int g   = lid >> 2;
    const int t4  = lid & 3;

    int tr, tc; pair_from_idx(blockIdx.x, tr, tc);
    const int i0 = tr * 128, l0 = tc * 128;
    const bool diag = (tr == tc);
    const int ops  = diag ? 1 : 2;
    const int nb   = blockIdx.y * (N_OBS / NSPLIT);

    const uint32_t sb = smem_u32(sm);
    const int wr = wid & 3;
    const int wc = wid >> 2;
    const int ibase = wr * 32, lbase = wc * 64;

    float c[2][8][4];
    #pragma unroll
    for (int mi = 0; mi < 2; mi++)
        #pragma unroll
        for (int ni = 0; ni < 8; ni++)
            #pragma unroll
            for (int t = 0; t < 4; t++) c[mi][ni][t] = 0.f;

    auto stage = [&](int ch, int buf) {
        const int n0 = nb + ch * 32;
        const int tot = ops << 9;
        for (int e = tid; e < tot; e += 256) {
            const int op  = e >> 9;
            const int idx = e & 511;
            const int row = idx >> 2;
            const int c16 = idx & 3;
            const int grow = (op ? l0 : i0) + row;
            cp_async16(sb + (uint32_t)(buf * B_BUF + op * B_OPB + row * B_ROWB + c16 * 16),
                       &g_sT[(size_t)grow * N_OBS + n0 + c16 * 8]);
        }
    };

    const uint32_t aOff0 = (uint32_t)((ibase + (lid & 15)) * B_ROWB + (lid >> 4) * 16);
    const uint32_t bRow  = (uint32_t)(lbase + ((lid >> 4) << 3) + (lid & 7));
    const uint32_t bOff0 = bRow * B_ROWB + ((lid >> 3) & 1) * 16;

    stage(0, 0);
    CP_COMMIT();

    for (int ch = 0; ch < B_NCH; ch++) {
        const int buf = ch & 1;
        if (ch + 1 < B_NCH) { stage(ch + 1, buf ^ 1); CP_COMMIT(); CP_WAIT1(); }
        else                { CP_WAIT0(); }
        __syncthreads();

        const uint32_t aBase = sb + buf * B_BUF;
        const uint32_t bBase = diag ? aBase : aBase + B_OPB;

        #pragma unroll
        for (int ks = 0; ks < 2; ks++) {
            uint32_t a[2][4];
            #pragma unroll
            for (int mi = 0; mi < 2; mi++)
                ldmatrix_x4(a[mi], aBase + aOff0 + (uint32_t)(mi * 16 * B_ROWB + ks * 32));
            #pragma unroll
            for (int p = 0; p < 4; p++) {
                uint32_t bb[4];
                ldmatrix_x4(bb, bBase + bOff0 + (uint32_t)(p * 16 * B_ROWB + ks * 32));
                #pragma unroll
                for (int mi = 0; mi < 2; mi++) {
                    mma_f16(c[mi][2 * p],     a[mi], &bb[0]);
                    mma_f16(c[mi][2 * p + 1], a[mi], &bb[2]);
                }
            }
        }
        __syncthreads();
    }

    const float sc = (2.0f / (float)KH) / (float)N_OBS;
    float* dst = &g_Mp[((size_t)blockIdx.y * NPAIR + blockIdx.x) * (128 * 128)];
    #pragma unroll
    for (int mi = 0; mi < 2; mi++) {
        const int rr = ibase + 16 * mi + g;
        #pragma unroll
        for (int ni = 0; ni < 8; ni++) {
            const int cc = lbase + 8 * ni + 2 * t4;
            float2 v0 = make_float2(c[mi][ni][0] * sc, c[mi][ni][1] * sc);
            float2 v1 = make_float2(c[mi][ni][2] * sc, c[mi][ni][3] * sc);
            *(float2*)&dst[(size_t)rr * 128 + cc]       = v0;
            *(float2*)&dst[(size_t)(rr + 8) * 128 + cc] = v1;
        }
    }
}

// ---------------------------------------------------------------------------
// Kernel C (fused R, wide-row stores): tile 4k x 256l -> per d, each k-row
// written as 1 KB contiguous (two warps) for DRAM write-burst efficiency.
// grid = (KH/256 = 4, KH/4 = 256) = 1024 CTAs, 256 threads, 5 CTAs/SM.
// ---------------------------------------------------------------------------
#define C_KT 4
#define C_LT 256
#define C_WPAD 260

__global__ void __launch_bounds__(256, 5) kernelC(const float* __restrict__ w,
                                                  float* __restrict__ out) {
    __shared__ __align__(16) float wld[32][C_WPAD];     // 33.3 KB (one 32-d half)
    __shared__ __align__(16) float Ms[C_KT][C_LT];      // 4 KB
    __shared__ float wks[DIN][C_KT + 1];                // 1.3 KB

    const int tid = threadIdx.x;
    const int l0  = blockIdx.x * C_LT;
    const int k0  = blockIdx.y * C_KT;
    const int kt  = k0 >> 7;
    const int ko  = k0 & 127;            // multiple of 4

    // ---- fused reduction: two 128-col halves, one pair each
    {
        const int lh  = tid >> 7;                       // which l-half
        const int t   = tid & 127;
        const int lt2 = (l0 >> 7) + lh;
        if (kt <= lt2) {
            const size_t pbase = (size_t)idx_from_pair(kt, lt2) * (128 * 128);
            const int kk  = t >> 5;                     // 0..3
            const int li4 = (t & 31) * 4;
            float4 v = make_float4(0.f, 0.f, 0.f, 0.f);
            #pragma unroll
            for (int s = 0; s < NSPLIT; s++) {
                const float4 p = *(const float4*)
                    &g_Mp[(size_t)s * NPAIR * (128 * 128) + pbase + (size_t)(ko + kk) * 128 + li4];
                v.x += p.x; v.y += p.y; v.z += p.z; v.w += p.w;
            }
            *(float4*)&Ms[kk][lh * 128 + li4] = v;
        } else {
            const size_t pbase = (size_t)idx_from_pair(lt2, kt) * (128 * 128);
            const int li = t;                           // 0..127
            float4 v = make_float4(0.f, 0.f, 0.f, 0.f);
            #pragma unroll
            for (int s = 0; s < NSPLIT; s++) {
                const float4 p = *(const float4*)
                    &g_Mp[(size_t)s * NPAIR * (128 * 128) + pbase + (size_t)li * 128 + ko];
                v.x += p.x; v.y += p.y; v.z += p.z; v.w += p.w;
            }
            Ms[0][lh * 128 + li] = v.x;
            Ms[1][lh * 128 + li] = v.y;
            Ms[2][lh * 128 + li] = v.z;
            Ms[3][lh * 128 + li] = v.w;
        }
    }

    for (int i = tid; i < C_KT * DIN; i += 256) {
        const int kk = i >> 6, d = i & 63;
        wks[d][kk] = w[(size_t)(k0 + kk) * DIN + d];
    }

    const int j     = tid >> 5;          // warp 0..7
    const int kk    = j & 3;             // k-row
    const int ch2   = j >> 2;            // l-half (128 cols)
    const int lane4 = (tid & 31) * 4;
    const int mcol  = ch2 * 128 + lane4;

    float4 M4;
    const size_t base = (size_t)(k0 + kk) * KH + l0 + mcol;

    #pragma unroll
    for (int h = 0; h < 2; h++) {
        __syncthreads();                 // h=0: Ms/wks ready; h=1: wld reads done
        for (int i = tid; i < 32 * C_LT; i += 256) {
            const int li = i >> 5, d = i & 31;
            wld[d][li] = w[(size_t)(l0 + li) * DIN + h * 32 + d];   // coalesced
        }
        __syncthreads();
        if (h == 0) M4 = *(const float4*)&Ms[kk][mcol];

        #pragma unroll 8
        for (int dd = 0; dd < 32; dd++) {
            const int d = h * 32 + dd;
            const float wk  = wks[d][kk];
            const float4 wl = *(const float4*)&wld[dd][mcol];
            float4 o;
            o.x = (M4.x * wk) * wl.x;
            o.y = (M4.y * wk) * wl.y;
            o.z = (M4.z * wk) * wl.z;
            o.w = (M4.w * wk) * wl.w;
            __stcs((float4*)&out[(size_t)d * (size_t)(KH * KH) + base], o);
        }
    }
}

// ---------------------------------------------------------------------------
extern "C" void kernel_launch(void* const* d_in, const int* in_sizes, int n_in,
                              void* d_out, int out_size) {
    (void)in_sizes; (void)n_in; (void)out_size;
    const float* x = (const float*)d_in[0];
    const float* w = (const float*)d_in[1];
    const float* b = (const float*)d_in[2];
    float* out = (float*)d_out;

    kernelP<<<(KH * DIN + N_OBS * DIN) / (4 * 256), 256>>>(x, w);
    kernelA_f16<<<dim3(KH / 64, N_OBS / 64), 256>>>(b);
    kernelB_f16<<<dim3(NPAIR, NSPLIT), 256>>>();
    kernelC<<<dim3(KH / C_LT, KH / C_KT), 256>>>(w, out);
}